// round 7
// baseline (speedup 1.0000x reference)
#include <cuda_runtime.h>

#define BLK 256   // 8 chains x 16 heads x 2 halves

// transformed weights: matrix-rep coords. coord(r,s,im) = (r*4+s)*2 + im
__device__ float g_Win2[16 * 6 * 32];   // [h][d][coord]
__device__ float g_bin2[16 * 32];       // [h][coord]
__device__ float g_Wout2[16 * 6 * 32];  // [h][d][coord]  (includes 1/4 factor)

// ---------------------------------------------------------------------------
// prep: build blade matrices of Cl(4,1) in M4(C) and fold basis change into
// the weights. Runs every launch (deterministic, trivial cost).
// ---------------------------------------------------------------------------
__global__ void prep_kernel(const float* __restrict__ Win,    // [6,512]
                            const float* __restrict__ bin,    // [512]
                            const float* __restrict__ Wout)   // [512,6]
{
    __shared__ float B[32][32];   // blade -> 32 matrix coords

    if (threadIdx.x == 0) {
        float gre[5][4][4], gim[5][4][4];
        for (int i = 0; i < 5; i++)
            for (int r = 0; r < 4; r++)
                for (int s = 0; s < 4; s++) { gre[i][r][s] = 0.f; gim[i][r][s] = 0.f; }
        // g0 = gamma1
        gre[0][0][3] = 1; gre[0][1][2] = 1; gre[0][2][1] = 1; gre[0][3][0] = 1;
        // g1 = gamma2
        gim[1][0][3] = -1; gim[1][1][2] = 1; gim[1][2][1] = -1; gim[1][3][0] = 1;
        // g2 = gamma3
        gre[2][0][2] = 1; gre[2][1][3] = -1; gre[2][2][0] = 1; gre[2][3][1] = -1;
        // g3 = gamma4 (square +1)
        gim[3][0][2] = 1; gim[3][1][3] = 1; gim[3][2][0] = -1; gim[3][3][1] = -1;
        // g4 = e5 = i*g0*g1*g2*g3 = diag(i,i,-i,-i)  (square -1)
        gim[4][0][0] = 1; gim[4][1][1] = 1; gim[4][2][2] = -1; gim[4][3][3] = -1;

        for (int a = 0; a < 32; a++) {
            float mre[4][4], mim[4][4];
            for (int r = 0; r < 4; r++)
                for (int s = 0; s < 4; s++) { mre[r][s] = (r == s) ? 1.f : 0.f; mim[r][s] = 0.f; }
            for (int i = 0; i < 5; i++) {
                if (!((a >> i) & 1)) continue;
                float tre[4][4], tim[4][4];
                for (int r = 0; r < 4; r++)
                    for (int s = 0; s < 4; s++) {
                        float xr = 0.f, xi = 0.f;
                        for (int k = 0; k < 4; k++) {
                            xr += mre[r][k] * gre[i][k][s] - mim[r][k] * gim[i][k][s];
                            xi += mre[r][k] * gim[i][k][s] + mim[r][k] * gre[i][k][s];
                        }
                        tre[r][s] = xr; tim[r][s] = xi;
                    }
                for (int r = 0; r < 4; r++)
                    for (int s = 0; s < 4; s++) { mre[r][s] = tre[r][s]; mim[r][s] = tim[r][s]; }
            }
            for (int r = 0; r < 4; r++)
                for (int s = 0; s < 4; s++) {
                    B[a][(r * 4 + s) * 2]     = mre[r][s];
                    B[a][(r * 4 + s) * 2 + 1] = mim[r][s];
                }
        }
    }
    __syncthreads();

    for (int idx = threadIdx.x; idx < 3072; idx += blockDim.x) {
        int d = idx / 512, rem = idx - d * 512;
        int h = rem >> 5, coord = rem & 31;
        float s = 0.f;
        for (int c = 0; c < 32; c++)
            s += Win[d * 512 + h * 32 + c] * B[c][coord];
        g_Win2[(h * 6 + d) * 32 + coord] = s;
    }
    for (int idx = threadIdx.x; idx < 512; idx += blockDim.x) {
        int h = idx >> 5, coord = idx & 31;
        float s = 0.f;
        for (int c = 0; c < 32; c++)
            s += bin[h * 32 + c] * B[c][coord];
        g_bin2[idx] = s;
    }
    for (int idx = threadIdx.x; idx < 3072; idx += blockDim.x) {
        int h = idx / 192, rem = idx - h * 192;
        int d = rem >> 5, coord = rem & 31;
        float s = 0.f;
        for (int c = 0; c < 32; c++)
            s += B[c][coord] * Wout[(h * 32 + c) * 6 + d];
        g_Wout2[(h * 6 + d) * 32 + coord] = 0.25f * s;
    }
}

// ---------------------------------------------------------------------------
// main scan. thread = (chain ci, head h, half f). Each thread owns matrix
// rows {2f, 2f+1} (16 coords). GP needs full psi (kept via shfl exchange)
// but only own rows of U. 2 warps/SMSP for latency hiding.
// lane = ci + 8*q, q = f + 2*(h&1), warp w: h = 2*w + (q>>1). partner = lane^8.
// shapes: B=16, S=256, N=64, D=6, H=16; x strides: b 98304, s 384, n 6
// ---------------------------------------------------------------------------
__global__ __launch_bounds__(BLK, 1)
void versor_kernel(const float* __restrict__ x,
                   const float* __restrict__ bout,   // [6]
                   float* __restrict__ out)
{
    __shared__ __align__(16) float sWin[16 * 196];   // [h][d][coord]
    __shared__ __align__(16) float sWout[16 * 196];  // [h][d][coord]
    __shared__ __align__(16) float sBin[16 * 36];    // [h][coord]
    __shared__ float sPart[2][32][50];               // [buf][h*2+f][ci*6+d]

    const int tid = threadIdx.x;
    const int ci  = tid & 7;              // chain within block
    const int q   = (tid >> 3) & 3;
    const int w   = tid >> 5;             // warp
    const int f   = q & 1;                // half (rows 2f, 2f+1)
    const int h   = 2 * w + (q >> 1);     // head
    const int b   = blockIdx.x >> 3;
    const int n0  = (blockIdx.x & 7) * 8;

    // ---- stage transformed weights into shared ----
    for (int i = tid; i < 3072; i += BLK) {
        int hh = i / 192, rr = i - hh * 192;
        sWin[hh * 196 + rr]  = g_Win2[i];
        sWout[hh * 196 + rr] = g_Wout2[i];
    }
    for (int i = tid; i < 512; i += BLK)
        sBin[(i >> 5) * 36 + (i & 31)] = g_bin2[i];
    __syncthreads();

    const float* xchain = x + (size_t)b * 98304 + (size_t)(n0 + ci) * 6;
    const float* wi = sWin  + h * 196 + f * 16;   // own-half coords, per-d stride 32
    const float* wo = sWout + h * 196 + f * 16;
    const float* bi = sBin  + h * 36  + f * 16;

    // reducer role (threads 0..47): chain rci, component rd
    const int  rci = tid / 6;
    const int  rd  = tid - rci * 6;
    const bool is_red = (tid < 48);
    const float boutr = __ldg(bout + (is_red ? rd : 0));
    const size_t obase = (size_t)b * 98304 + (size_t)(n0 + (is_red ? rci : 0)) * 6 + rd;

    const float ff = (float)f;            // 1 if owning rows 2,3

    // full psi in global coords; psi0 = identity
    float Pg[32];
#pragma unroll
    for (int k = 0; k < 32; k++) Pg[k] = 0.0f;
    Pg[0] = 1.0f; Pg[10] = 1.0f; Pg[20] = 1.0f; Pg[30] = 1.0f;

    for (int t = 0; t < 256; t++) {
        // ---- load x_t[6] ----
        const float2* xp2 = (const float2*)(xchain + (size_t)t * 384);
        float2 v0 = __ldg(xp2), v1 = __ldg(xp2 + 1), v2 = __ldg(xp2 + 2);
        const float xv[6] = { v0.x, v0.y, v1.x, v1.y, v2.x, v2.y };

        // ---- embed own-half coords: u[16] = bin' + x @ Win' ----
        float u[16];
#pragma unroll
        for (int c4 = 0; c4 < 4; c4++) {
            float4 bb = *(const float4*)(bi + c4 * 4);
            u[c4 * 4 + 0] = bb.x; u[c4 * 4 + 1] = bb.y;
            u[c4 * 4 + 2] = bb.z; u[c4 * 4 + 3] = bb.w;
        }
#pragma unroll
        for (int d = 0; d < 6; d++) {
            float xd = xv[d];
#pragma unroll
            for (int c4 = 0; c4 < 4; c4++) {
                float4 wv = *(const float4*)(wi + d * 32 + c4 * 4);
                u[c4 * 4 + 0] = fmaf(xd, wv.x, u[c4 * 4 + 0]);
                u[c4 * 4 + 1] = fmaf(xd, wv.y, u[c4 * 4 + 1]);
                u[c4 * 4 + 2] = fmaf(xd, wv.z, u[c4 * 4 + 2]);
                u[c4 * 4 + 3] = fmaf(xd, wv.w, u[c4 * 4 + 3]);
            }
        }

        // ---- +identity (own rows): f=0 -> u[0],u[10]; f=1 -> u[4],u[14] ----
        // (delta_r normalize skipped: GP bilinear + post-normalize => scale cancels)
        u[0]  += 1.0f - ff;   u[10] += 1.0f - ff;
        u[4]  += ff;          u[14] += ff;

        // ---- GP own rows: acc[rl][s] = sum_k U[2f+rl][k] * Pg[k][s] ----
        float acc[16];
#pragma unroll
        for (int rl = 0; rl < 2; rl++) {
#pragma unroll
            for (int s = 0; s < 4; s++) {
                float cre = 0.f, cim = 0.f;
#pragma unroll
                for (int k = 0; k < 4; k++) {
                    float are = u[(rl * 4 + k) * 2], aim = u[(rl * 4 + k) * 2 + 1];
                    float bre = Pg[(k * 4 + s) * 2], bim = Pg[(k * 4 + s) * 2 + 1];
                    cre = fmaf(are, bre, cre);
                    cre = fmaf(-aim, bim, cre);
                    cim = fmaf(are, bim, cim);
                    cim = fmaf(aim, bre, cim);
                }
                acc[(rl * 4 + s) * 2]     = cre;
                acc[(rl * 4 + s) * 2 + 1] = cim;
            }
        }

        // ---- normalize: coeff norm^2 = frob^2/4, frob over both halves ----
        float part;
        {
            float s0 = 0.f, s1 = 0.f, s2 = 0.f, s3 = 0.f;
#pragma unroll
            for (int c = 0; c < 16; c += 4) {
                s0 = fmaf(acc[c + 0], acc[c + 0], s0);
                s1 = fmaf(acc[c + 1], acc[c + 1], s1);
                s2 = fmaf(acc[c + 2], acc[c + 2], s2);
                s3 = fmaf(acc[c + 3], acc[c + 3], s3);
            }
            part = (s0 + s1) + (s2 + s3);
        }
        float tot = part + __shfl_xor_sync(0xffffffffu, part, 8);
        float rn  = rsqrtf(0.25f * tot + 1e-12f);

        float Pown[16];
#pragma unroll
        for (int c = 0; c < 16; c++) Pown[c] = acc[c] * rn;

        // ---- reassemble full psi: exchange halves with partner (lane^8) ----
#pragma unroll
        for (int c = 0; c < 16; c++) {
            float oth = __shfl_xor_sync(0xffffffffu, Pown[c], 8);
            Pg[c]      = f ? oth     : Pown[c];
            Pg[16 + c] = f ? Pown[c] : oth;
        }

        // ---- projection partial over own coords ----
        float pd[6];
#pragma unroll
        for (int d = 0; d < 6; d++) {
            float a0 = 0.f, a1 = 0.f, a2 = 0.f, a3 = 0.f;
#pragma unroll
            for (int c4 = 0; c4 < 4; c4++) {
                float4 wv = *(const float4*)(wo + d * 32 + c4 * 4);
                a0 = fmaf(Pown[c4 * 4 + 0], wv.x, a0);
                a1 = fmaf(Pown[c4 * 4 + 1], wv.y, a1);
                a2 = fmaf(Pown[c4 * 4 + 2], wv.z, a2);
                a3 = fmaf(Pown[c4 * 4 + 3], wv.w, a3);
            }
            pd[d] = (a0 + a1) + (a2 + a3);
        }

        // ---- cross-(head,half) reduce: 32 partial rows, one barrier ----
        float* pp = &sPart[t & 1][h * 2 + f][ci * 6];
#pragma unroll
        for (int d = 0; d < 6; d++) pp[d] = pd[d];
        __syncthreads();

        if (is_red) {
            float s = boutr;
#pragma unroll
            for (int rr = 0; rr < 32; rr++)
                s += sPart[t & 1][rr][rci * 6 + rd];
            float xvv = __ldg(x + obase + (size_t)t * 384);
            out[obase + (size_t)t * 384] = xvv + s;
        }
    }
}

extern "C" void kernel_launch(void* const* d_in, const int* in_sizes, int n_in,
                              void* d_out, int out_size)
{
    const float* x    = (const float*)d_in[0];
    const float* Win  = (const float*)d_in[1];
    const float* bin  = (const float*)d_in[2];
    const float* Wout = (const float*)d_in[3];
    const float* bout = (const float*)d_in[4];
    float* out = (float*)d_out;

    prep_kernel<<<1, 256>>>(Win, bin, Wout);
    versor_kernel<<<128, BLK>>>(x, bout, out);
}